// round 15
// baseline (speedup 1.0000x reference)
#include <cuda_runtime.h>
#include <cuda_bf16.h>

// Shape fixed for this dataset entry
#define NN 8
#define LL 8192
#define SS 8192
#define HH 8
#define RS 256              // floats per token row (H*D)
#define NH 64               // N*H

#define P1CH 64             // phase1 chunks per head
#define P1TOK 128           // tokens per warp-chunk
#define P1TILE 8            // tokens per pipeline stage (R5 measured-best)
#define P1NT (P1TOK/P1TILE) // 16 stages
#define PART 1056           // 1024 KV (f32x2-pair layout) + 32 Ksum

#define P2C 16              // phase2 L-chunks

// Deterministic scratch
__device__ __align__(16) float g_part[P1CH * NH * PART];   // ~17.3 MB
__device__ __align__(16) float g_red [NH * PART];          // reduced states

typedef unsigned long long u64;

__device__ __forceinline__ u64 fma2(u64 a, u64 b, u64 c) {
    u64 d;
    asm("fma.rn.f32x2 %0, %1, %2, %3;" : "=l"(d) : "l"(a), "l"(b), "l"(c));
    return d;
}
__device__ __forceinline__ u64 dup2(float v) {
    u64 d;
    asm("mov.b64 %0, {%1, %1};" : "=l"(d) : "f"(v));
    return d;
}
__device__ __forceinline__ float2 unp(u64 a) {
    float2 r;
    asm("mov.b64 {%0, %1}, %2;" : "=f"(r.x), "=f"(r.y) : "l"(a));
    return r;
}
__device__ __forceinline__ float elu1(float x) {
    return x > 0.0f ? x + 1.0f : __expf(x);   // elu(x)+1 = exp(x) for x<=0
}

// ---------------------------------------------------------------------------
// Phase 1 (R5 structure; ONLY change vs R14: broadcast loads are explicit
// LDS.128 instead of 16x LDS.64 — halves the contended LDS issue stream that
// the floor model says is the wall). Each WARP owns a full 32x32 KV
// accumulator (f32x2 pairs, lane = v column) for a private 128-token chunk.
// elu(K) staged through warp-private smem (syncwarp only), V in registers.
// 8 K + 8 V rows prefetched per stage. Epilogue: coalesced STG.64.
// Partial layout: p = j*64 + 2v + e  <->  KV[2j+e][v];  p=1024+d -> Ksum[d].
// ---------------------------------------------------------------------------
__global__ void __launch_bounds__(256)
phase1_kernel(const float* __restrict__ K, const float* __restrict__ V)
{
    __shared__ __align__(16) float sK[8][P1TILE * 32];   // per-warp stage

    const int tid = threadIdx.x;
    const int w = tid >> 5, lane = tid & 31;
    const int W = blockIdx.x * 8 + w;        // global warp id, 0..4095
    const int nh = W >> 6, chunk = W & (P1CH - 1);
    const int n = nh >> 3, h = nh & 7;

    const size_t tokbase = ((size_t)n * SS + (size_t)chunk * P1TOK) * RS + h * 32 + lane;
    const float* Kp = K + tokbase;
    const float* Vp = V + tokbase;
    float* sk = &sK[w][0];

    u64 acc[16];
    #pragma unroll
    for (int j = 0; j < 16; j++) acc[j] = 0ULL;
    float ksum = 0.f;

    float kr[P1TILE], vr[P1TILE];
    #pragma unroll
    for (int i = 0; i < P1TILE; i++) {       // prefetch stage 0
        kr[i] = Kp[(size_t)i * RS];
        vr[i] = Vp[(size_t)i * RS];
    }

    for (int t = 0; t < P1NT; ++t) {
        float vcur[P1TILE];
        #pragma unroll
        for (int i = 0; i < P1TILE; i++) {
            float e = elu1(kr[i]);
            ksum += e;
            sk[i * 32 + lane] = e;
            vcur[i] = vr[i];
        }
        __syncwarp();

        if (t + 1 < P1NT) {                  // prefetch next stage (front-batched)
            const float* Kn = Kp + (size_t)(t + 1) * P1TILE * RS;
            const float* Vn = Vp + (size_t)(t + 1) * P1TILE * RS;
            #pragma unroll
            for (int i = 0; i < P1TILE; i++) kr[i] = Kn[(size_t)i * RS];
            #pragma unroll
            for (int i = 0; i < P1TILE; i++) vr[i] = Vn[(size_t)i * RS];
        }

        #pragma unroll
        for (int i = 0; i < P1TILE; i++) {
            u64 v2 = dup2(vcur[i]);
            const ulonglong2* k2 = (const ulonglong2*)(sk + i * 32);  // LDS.128 bcast
            #pragma unroll
            for (int j = 0; j < 8; j++) {
                ulonglong2 kk = k2[j];
                acc[2 * j + 0] = fma2(kk.x, v2, acc[2 * j + 0]);
                acc[2 * j + 1] = fma2(kk.y, v2, acc[2 * j + 1]);
            }
        }
        __syncwarp();
    }

    float* gp = g_part + ((size_t)chunk * NH + nh) * PART;
    #pragma unroll
    for (int j = 0; j < 16; j++)             // coalesced 256B STG.64 per j
        *(u64*)&gp[j * 64 + lane * 2] = acc[j];
    gp[1024 + lane] = ksum;
}

// ---------------------------------------------------------------------------
// Mid: reduce 64 chunk partials per head. One thread per (nh, f) element.
// ---------------------------------------------------------------------------
__global__ void __launch_bounds__(256)
reduce_kernel()
{
    const int g = blockIdx.x * 256 + threadIdx.x;   // 0 .. 64*1056-1
    if (g >= NH * PART) return;
    const int nh = g / PART, f = g - nh * PART;
    float s = 0.f;
    #pragma unroll 8
    for (int c = 0; c < P1CH; c++)
        s += g_part[((size_t)c * NH + nh) * PART + f];
    g_red[(size_t)nh * PART + f] = s;
}

// ---------------------------------------------------------------------------
// Phase 2 (R10/R14 measured, ~56us — unchanged): out = phi(Q) @ KV / Z.
// Lane holds KV column `lane` as 16 packed pairs (from g_red). 8 rows per
// pipeline stage; q broadcast via LDS.128; Z-seed folded into elu step;
// 8 interleaved shuffle butterflies. Warp-private, no block syncs.
// ---------------------------------------------------------------------------
__global__ void __launch_bounds__(256)
phase2_kernel(const float* __restrict__ Q, float* __restrict__ out)
{
    __shared__ __align__(16) float qbuf[8][8][32];

    const int tid = threadIdx.x;
    const int w = tid >> 5, lane = tid & 31;
    const int nh = blockIdx.x, chunk = blockIdx.y;   // 64 x 16
    const int n = nh >> 3, h = nh & 7;

    const float* red = g_red + (size_t)nh * PART;
    u64 kv[16];
    #pragma unroll
    for (int j = 0; j < 16; j++)
        kv[j] = *(const u64*)&red[j * 64 + lane * 2];
    const float ks = red[1024 + lane];

    const size_t base = ((size_t)n * LL + (size_t)chunk * 512 + w * 64) * RS + h * 32 + lane;
    const float* Qp = Q + base;
    float*       Op = out + base;

    float qr[8];
    #pragma unroll
    for (int i = 0; i < 8; i++) qr[i] = Qp[(size_t)i * RS];

    for (int g = 0; g < 8; ++g) {
        float t[8];
        #pragma unroll
        for (int i = 0; i < 8; i++) {        // elu + stage + Z-seed (qf not kept)
            float qf = elu1(qr[i]);
            qbuf[w][i][lane] = qf;
            t[i] = qf * ks;
        }
        __syncwarp();

        if (g + 1 < 8) {                     // prefetch next 8 rows
            const float* Qn = Qp + (size_t)(g + 1) * 8 * RS;
            #pragma unroll
            for (int i = 0; i < 8; i++) qr[i] = Qn[(size_t)i * RS];
        }

        u64 a[8];
        #pragma unroll
        for (int i = 0; i < 8; i++) a[i] = 0ULL;
        #pragma unroll
        for (int j = 0; j < 8; j++) {
            #pragma unroll
            for (int i = 0; i < 8; i++) {    // LDS.128 bcast, 8 indep chains
                ulonglong2 qq = *((const ulonglong2*)qbuf[w][i] + j);
                a[i] = fma2(qq.x, kv[2 * j + 0], a[i]);
                a[i] = fma2(qq.y, kv[2 * j + 1], a[i]);
            }
        }

        #pragma unroll
        for (int m = 16; m >= 1; m >>= 1) {  // 8 interleaved butterflies
            #pragma unroll
            for (int i = 0; i < 8; i++)
                t[i] += __shfl_xor_sync(0xFFFFFFFFu, t[i], m);
        }

        #pragma unroll
        for (int i = 0; i < 8; i++) {
            float2 u = unp(a[i]);
            Op[(size_t)(g * 8 + i) * RS] = (u.x + u.y) * __fdividef(1.f, t[i] + 1e-6f);
        }
        __syncwarp();
    }
}

extern "C" void kernel_launch(void* const* d_in, const int* in_sizes, int n_in,
                              void* d_out, int out_size)
{
    const float* queries = (const float*)d_in[0];
    const float* keys    = (const float*)d_in[1];
    const float* values  = (const float*)d_in[2];
    float* out = (float*)d_out;

    phase1_kernel<<<NH * P1CH / 8, 256>>>(keys, values);
    reduce_kernel<<<(NH * PART + 255) / 256, 256>>>();
    phase2_kernel<<<dim3(NH, P2C), 256>>>(queries, out);
}